// round 6
// baseline (speedup 1.0000x reference)
#include <cuda_runtime.h>
#include <cstdint>
#include <math.h>

// Problem constants
#define BATCH 2
#define SEQ   1024
#define TOK   (BATCH*SEQ)      // 2048
#define DMODEL 1024
#define NHEAD 16
#define DK    64
#define FF    4096
#define NLAYER 4
#define LNEPS 1e-5f

#define H_ELEMS ((size_t)TOK * DMODEL)
#define AW_PER_LAYER ((size_t)BATCH * NHEAD * SEQ * SEQ)

// ------------------------- scratch (static device globals) -------------------------
__device__ float g_h  [TOK * DMODEL];
__device__ float g_q  [TOK * DMODEL];
__device__ float g_k  [TOK * DMODEL];
__device__ float g_v  [TOK * DMODEL];
__device__ float g_ctx[TOK * DMODEL];
__device__ float g_res[TOK * DMODEL];
__device__ float g_ff [TOK * FF];

// ------------------------------ tf32 helpers ---------------------------------------
__device__ __forceinline__ float f2tf32f(float x) {
    uint32_t r;
    asm("cvt.rna.tf32.f32 %0, %1;" : "=r"(r) : "f"(x));
    return __uint_as_float(r);
}

__device__ __forceinline__ void mma1688(float c[4], const float a[4], const float b[2]) {
    asm volatile(
        "mma.sync.aligned.m16n8k8.row.col.f32.tf32.tf32.f32 "
        "{%0,%1,%2,%3}, {%4,%5,%6,%7}, {%8,%9}, {%0,%1,%2,%3};"
        : "+f"(c[0]), "+f"(c[1]), "+f"(c[2]), "+f"(c[3])
        : "r"(__float_as_uint(a[0])), "r"(__float_as_uint(a[1])),
          "r"(__float_as_uint(a[2])), "r"(__float_as_uint(a[3])),
          "r"(__float_as_uint(b[0])), "r"(__float_as_uint(b[1])));
}

// ===================== templated tf32 mma.sync GEMM core ============================
template <int BM, int BN, int BK, int WM, int WN, int TRANSB, int RELU, int HASBIAS>
__device__ __forceinline__ void gemm_core(
    const float* __restrict__ A, int lda,
    const float* __restrict__ B, int ldb,
    const float* __restrict__ bias,
    float* __restrict__ C, int ldc,
    int K, float scale)
{
    static_assert(BK == 32, "BK must be 32");
    constexpr int BKP = BK + 4;
    constexpr int BNP = BN + 8;
    __shared__ float As[BM][BKP];
    __shared__ float Bs[BK][BNP];

    const int tid = threadIdx.x;
    const int m0 = blockIdx.y * BM;
    const int n0 = blockIdx.x * BN;
    A += (size_t)m0 * lda;
    if (TRANSB) B += (size_t)n0 * ldb;
    else        B += n0;
    C += (size_t)m0 * ldc + n0;
    if (HASBIAS) bias += n0;

    constexpr int LA = BM * BK / (4 * 256);
    constexpr int LB = BK * BN / (4 * 256);
    float4 pa[LA], pb[LB];

    const int NC = K / BK;

    auto loadA = [&](int c) {
        #pragma unroll
        for (int t = 0; t < LA; t++) {
            int i = tid + t * 256;
            int r = i >> 3;
            int cc = (i & 7) * 4;
            pa[t] = *(const float4*)(A + (size_t)r * lda + c * BK + cc);
        }
    };
    auto loadB = [&](int c) {
        if (TRANSB) {
            #pragma unroll
            for (int t = 0; t < LB; t++) {
                int i = tid + t * 256;
                int n = i >> 3;
                int kg = (i & 7) * 4;
                pb[t] = *(const float4*)(B + (size_t)n * ldb + c * BK + kg);
            }
        } else {
            #pragma unroll
            for (int t = 0; t < LB; t++) {
                int i = tid + t * 256;
                int r = i / (BN / 4);
                int cc = (i % (BN / 4)) * 4;
                pb[t] = *(const float4*)(B + (size_t)(c * BK + r) * ldb + cc);
            }
        }
    };
    auto storeS = [&]() {
        #pragma unroll
        for (int t = 0; t < LA; t++) {
            int i = tid + t * 256;
            int r = i >> 3;
            int cc = (i & 7) * 4;
            float4 o = make_float4(f2tf32f(pa[t].x), f2tf32f(pa[t].y),
                                   f2tf32f(pa[t].z), f2tf32f(pa[t].w));
            *(float4*)&As[r][cc] = o;
        }
        if (TRANSB) {
            #pragma unroll
            for (int t = 0; t < LB; t++) {
                int i = tid + t * 256;
                int n = i >> 3;
                int kg = (i & 7) * 4;
                Bs[kg + 0][n] = f2tf32f(pb[t].x);
                Bs[kg + 1][n] = f2tf32f(pb[t].y);
                Bs[kg + 2][n] = f2tf32f(pb[t].z);
                Bs[kg + 3][n] = f2tf32f(pb[t].w);
            }
        } else {
            #pragma unroll
            for (int t = 0; t < LB; t++) {
                int i = tid + t * 256;
                int r = i / (BN / 4);
                int cc = (i % (BN / 4)) * 4;
                float4 o = make_float4(f2tf32f(pb[t].x), f2tf32f(pb[t].y),
                                       f2tf32f(pb[t].z), f2tf32f(pb[t].w));
                *(float4*)&Bs[r][cc] = o;
            }
        }
    };

    constexpr int MS = WM / 16;
    constexpr int NS = WN / 8;
    constexpr int NWM = BM / WM;
    const int w = tid >> 5, lane = tid & 31;
    const int wm = (w % NWM) * WM;
    const int wn = (w / NWM) * WN;
    const int g = lane >> 2, tg = lane & 3;

    float acc[MS][NS][4];
    #pragma unroll
    for (int ms = 0; ms < MS; ms++)
        #pragma unroll
        for (int ns = 0; ns < NS; ns++)
            #pragma unroll
            for (int r = 0; r < 4; r++) acc[ms][ns][r] = 0.0f;

    loadA(0);
    loadB(0);

    for (int c = 0; c < NC; c++) {
        if (c) __syncthreads();
        storeS();
        __syncthreads();
        if (c + 1 < NC) { loadA(c + 1); loadB(c + 1); }

        #pragma unroll
        for (int ks = 0; ks < BK / 8; ks++) {
            float af[MS][4], bf[NS][2];
            #pragma unroll
            for (int ms = 0; ms < MS; ms++) {
                int row = wm + ms * 16 + g;
                int col = ks * 8 + tg;
                af[ms][0] = As[row][col];
                af[ms][1] = As[row + 8][col];
                af[ms][2] = As[row][col + 4];
                af[ms][3] = As[row + 8][col + 4];
            }
            #pragma unroll
            for (int ns = 0; ns < NS; ns++) {
                int bc = wn + ns * 8 + g;
                bf[ns][0] = Bs[ks * 8 + tg][bc];
                bf[ns][1] = Bs[ks * 8 + tg + 4][bc];
            }
            #pragma unroll
            for (int ms = 0; ms < MS; ms++)
                #pragma unroll
                for (int ns = 0; ns < NS; ns++)
                    mma1688(acc[ms][ns], af[ms], bf[ns]);
        }
    }

    #pragma unroll
    for (int ms = 0; ms < MS; ms++) {
        #pragma unroll
        for (int ns = 0; ns < NS; ns++) {
            int row = wm + ms * 16 + g;
            int col = wn + ns * 8 + tg * 2;
            float b0 = 0.0f, b1 = 0.0f;
            if (HASBIAS) { b0 = bias[col]; b1 = bias[col + 1]; }
            float v0 = acc[ms][ns][0] * scale + b0;
            float v1 = acc[ms][ns][1] * scale + b1;
            float v2 = acc[ms][ns][2] * scale + b0;
            float v3 = acc[ms][ns][3] * scale + b1;
            if (RELU) {
                v0 = fmaxf(v0, 0.0f); v1 = fmaxf(v1, 0.0f);
                v2 = fmaxf(v2, 0.0f); v3 = fmaxf(v3, 0.0f);
            }
            float2 o0 = make_float2(v0, v1);
            float2 o1 = make_float2(v2, v3);
            *(float2*)&C[(size_t)row * ldc + col] = o0;
            *(float2*)&C[(size_t)(row + 8) * ldc + col] = o1;
        }
    }
}

// ------------------------------- entry kernels --------------------------------------
struct QKV3 {
    const float* W[3];
    const float* b[3];
    float* o[3];
};

template <int RELU>
__global__ __launch_bounds__(256) void gemm_plain(const float* __restrict__ A,
                                                  const float* __restrict__ B,
                                                  const float* __restrict__ bias,
                                                  float* __restrict__ C, int N, int K) {
    gemm_core<128, 128, 32, 64, 32, 0, RELU, 1>(A, K, B, N, bias, C, N, K, 1.0f);
}

__global__ __launch_bounds__(256) void gemm_qkv(const float* __restrict__ A, QKV3 p) {
    int z = blockIdx.z;
    gemm_core<128, 128, 32, 64, 32, 0, 0, 1>(A, DMODEL, p.W[z], DMODEL, p.b[z],
                                              p.o[z], DMODEL, DMODEL, 1.0f);
}

// ================= fused attention: S=QK^T, softmax, write P, ctx=P@V ===============
// grid (SEQ/128, BATCH*NHEAD), 256 threads. Two-pass softmax, P materialized once
// into d_out and consumed from smem for P@V.
// K tile is stored TRANSPOSED in smem: KsT[dim][token] (B operand must be [k][n]).
#define KST_LD 132
#define FA_SMEM_FLOATS (128*68 + 64*KST_LD + 128*72 + 128*132 + 4*128 + 128 + 128)
#define FA_SMEM_BYTES  (FA_SMEM_FLOATS * 4)

__global__ __launch_bounds__(256) void attn_fused(const float* __restrict__ q,
                                                  const float* __restrict__ k,
                                                  const float* __restrict__ v,
                                                  float* __restrict__ aw,
                                                  float* __restrict__ ctx) {
    extern __shared__ float sm[];
    float* Qs   = sm;                     // [128][68]   queries x dims
    float* KsT  = Qs + 128 * 68;          // [64][132]   dims x tokens (transposed!)
    float* Vs   = KsT + 64 * KST_LD;      // [128][72]   tokens x dims
    float* Ps   = Vs + 128 * 72;          // [128][132]  queries x tokens
    float* red  = Ps + 128 * 132;         // [4][128]
    float* mrow = red + 4 * 128;          // [128]
    float* srow = mrow + 128;             // [128]

    const int tid = threadIdx.x;
    const int mt = blockIdx.x, bh = blockIdx.y;
    const int b = bh >> 4, hh = bh & 15;
    const float* qb = q + (size_t)(b * SEQ + mt * 128) * DMODEL + hh * DK;
    const float* kb = k + (size_t)b * SEQ * DMODEL + hh * DK;
    const float* vb = v + (size_t)b * SEQ * DMODEL + hh * DK;
    float* awb = aw + (size_t)bh * SEQ * SEQ + (size_t)(mt * 128) * SEQ;

    const int w = tid >> 5, lane = tid & 31, g = lane >> 2, tg = lane & 3;
    // S tile (128x128): warp grid 2(M) x 4(N), warp tile 64x32
    const int wm = (w & 1) * 64, wn = (w >> 1) * 32, wni = w >> 1;
    // PV tile (128x64): warp grid 4(M) x 2(N), warp tile 32x32
    const int wm2 = (w & 3) * 32, wn2 = (w >> 2) * 32;

    // ---- load Q tile once (tf32-rounded) ----
    #pragma unroll
    for (int t = 0; t < 8; t++) {
        int i = tid + t * 256;
        int r = i >> 4, c = (i & 15) * 4;
        float4 x = *(const float4*)(qb + (size_t)r * DMODEL + c);
        float4 o = make_float4(f2tf32f(x.x), f2tf32f(x.y), f2tf32f(x.z), f2tf32f(x.w));
        *(float4*)&Qs[r * 68 + c] = o;
    }
    if (tid < 128) { mrow[tid] = -INFINITY; srow[tid] = 0.0f; }
    __syncthreads();

    // =========================== PASS 1: row max & sum ==============================
    for (int kt = 0; kt < 8; kt++) {
        // load K tile TRANSPOSED: KsT[dim][token]
        #pragma unroll
        for (int t = 0; t < 8; t++) {
            int i = tid + t * 256;
            int r = i >> 4, c = (i & 15) * 4;     // r = token, c = dim base
            float4 x = *(const float4*)(kb + (size_t)(kt * 128 + r) * DMODEL + c);
            KsT[(c + 0) * KST_LD + r] = f2tf32f(x.x);
            KsT[(c + 1) * KST_LD + r] = f2tf32f(x.y);
            KsT[(c + 2) * KST_LD + r] = f2tf32f(x.z);
            KsT[(c + 3) * KST_LD + r] = f2tf32f(x.w);
        }
        __syncthreads();

        float acc[4][4][4];
        #pragma unroll
        for (int ms = 0; ms < 4; ms++)
            #pragma unroll
            for (int ns = 0; ns < 4; ns++)
                #pragma unroll
                for (int r = 0; r < 4; r++) acc[ms][ns][r] = 0.0f;

        #pragma unroll
        for (int ks = 0; ks < 8; ks++) {
            float af[4][4], bf[4][2];
            #pragma unroll
            for (int ms = 0; ms < 4; ms++) {
                int row = wm + ms * 16 + g, col = ks * 8 + tg;
                af[ms][0] = Qs[row * 68 + col];
                af[ms][1] = Qs[(row + 8) * 68 + col];
                af[ms][2] = Qs[row * 68 + col + 4];
                af[ms][3] = Qs[(row + 8) * 68 + col + 4];
            }
            #pragma unroll
            for (int ns = 0; ns < 4; ns++) {
                int bc = wn + ns * 8 + g;            // token
                bf[ns][0] = KsT[(ks * 8 + tg) * KST_LD + bc];
                bf[ns][1] = KsT[(ks * 8 + tg + 4) * KST_LD + bc];
            }
            #pragma unroll
            for (int ms = 0; ms < 4; ms++)
                #pragma unroll
                for (int ns = 0; ns < 4; ns++)
                    mma1688(acc[ms][ns], af[ms], bf[ns]);
        }
        #pragma unroll
        for (int ms = 0; ms < 4; ms++)
            #pragma unroll
            for (int ns = 0; ns < 4; ns++)
                #pragma unroll
                for (int r = 0; r < 4; r++) acc[ms][ns][r] *= 0.125f;

        // row max of this tile
        #pragma unroll
        for (int ms = 0; ms < 4; ms++) {
            #pragma unroll
            for (int half = 0; half < 2; half++) {
                float rm = -INFINITY;
                #pragma unroll
                for (int ns = 0; ns < 4; ns++)
                    rm = fmaxf(rm, fmaxf(acc[ms][ns][half * 2], acc[ms][ns][half * 2 + 1]));
                rm = fmaxf(rm, __shfl_xor_sync(0xffffffffu, rm, 1));
                rm = fmaxf(rm, __shfl_xor_sync(0xffffffffu, rm, 2));
                if (tg == 0) red[wni * 128 + wm + ms * 16 + half * 8 + g] = rm;
            }
        }
        __syncthreads();
        if (tid < 128) {
            float tm = fmaxf(fmaxf(red[tid], red[128 + tid]),
                             fmaxf(red[256 + tid], red[384 + tid]));
            float mo = mrow[tid];
            float mn = fmaxf(mo, tm);
            srow[tid] *= expf(mo - mn);
            mrow[tid] = mn;
        }
        __syncthreads();
        // row sum of exp
        #pragma unroll
        for (int ms = 0; ms < 4; ms++) {
            #pragma unroll
            for (int half = 0; half < 2; half++) {
                int row = wm + ms * 16 + half * 8 + g;
                float mr = mrow[row];
                float rs = 0.0f;
                #pragma unroll
                for (int ns = 0; ns < 4; ns++)
                    rs += expf(acc[ms][ns][half * 2] - mr) + expf(acc[ms][ns][half * 2 + 1] - mr);
                rs += __shfl_xor_sync(0xffffffffu, rs, 1);
                rs += __shfl_xor_sync(0xffffffffu, rs, 2);
                if (tg == 0) red[wni * 128 + row] = rs;
            }
        }
        __syncthreads();
        if (tid < 128)
            srow[tid] += red[tid] + red[128 + tid] + red[256 + tid] + red[384 + tid];
        __syncthreads();
    }

    if (tid < 128) srow[tid] = 1.0f / srow[tid];
    __syncthreads();

    // ================== PASS 2: recompute S, write P, accumulate P@V ================
    float acc2[2][4][4];
    #pragma unroll
    for (int ms = 0; ms < 2; ms++)
        #pragma unroll
        for (int ns = 0; ns < 4; ns++)
            #pragma unroll
            for (int r = 0; r < 4; r++) acc2[ms][ns][r] = 0.0f;

    for (int kt = 0; kt < 8; kt++) {
        #pragma unroll
        for (int t = 0; t < 8; t++) {
            int i = tid + t * 256;
            int r = i >> 4, c = (i & 15) * 4;
            float4 x = *(const float4*)(kb + (size_t)(kt * 128 + r) * DMODEL + c);
            KsT[(c + 0) * KST_LD + r] = f2tf32f(x.x);
            KsT[(c + 1) * KST_LD + r] = f2tf32f(x.y);
            KsT[(c + 2) * KST_LD + r] = f2tf32f(x.z);
            KsT[(c + 3) * KST_LD + r] = f2tf32f(x.w);
            float4 y = *(const float4*)(vb + (size_t)(kt * 128 + r) * DMODEL + c);
            float4 p = make_float4(f2tf32f(y.x), f2tf32f(y.y), f2tf32f(y.z), f2tf32f(y.w));
            *(float4*)&Vs[r * 72 + c] = p;
        }
        __syncthreads();

        float acc[4][4][4];
        #pragma unroll
        for (int ms = 0; ms < 4; ms++)
            #pragma unroll
            for (int ns = 0; ns < 4; ns++)
                #pragma unroll
                for (int r = 0; r < 4; r++) acc[ms][ns][r] = 0.0f;

        #pragma unroll
        for (int ks = 0; ks < 8; ks++) {
            float af[4][4], bf[4][2];
            #pragma unroll
            for (int ms = 0; ms < 4; ms++) {
                int row = wm + ms * 16 + g, col = ks * 8 + tg;
                af[ms][0] = Qs[row * 68 + col];
                af[ms][1] = Qs[(row + 8) * 68 + col];
                af[ms][2] = Qs[row * 68 + col + 4];
                af[ms][3] = Qs[(row + 8) * 68 + col + 4];
            }
            #pragma unroll
            for (int ns = 0; ns < 4; ns++) {
                int bc = wn + ns * 8 + g;
                bf[ns][0] = KsT[(ks * 8 + tg) * KST_LD + bc];
                bf[ns][1] = KsT[(ks * 8 + tg + 4) * KST_LD + bc];
            }
            #pragma unroll
            for (int ms = 0; ms < 4; ms++)
                #pragma unroll
                for (int ns = 0; ns < 4; ns++)
                    mma1688(acc[ms][ns], af[ms], bf[ns]);
        }

        // P = exp(S*scale - m) / sum  -> smem (tf32) + gmem (fp32)
        #pragma unroll
        for (int ms = 0; ms < 4; ms++) {
            int row0 = wm + ms * 16 + g;
            int row1 = row0 + 8;
            float m0 = mrow[row0], s0 = srow[row0];
            float m1 = mrow[row1], s1 = srow[row1];
            #pragma unroll
            for (int ns = 0; ns < 4; ns++) {
                int col = wn + ns * 8 + tg * 2;
                float p0 = expf(acc[ms][ns][0] * 0.125f - m0) * s0;
                float p1 = expf(acc[ms][ns][1] * 0.125f - m0) * s0;
                float p2 = expf(acc[ms][ns][2] * 0.125f - m1) * s1;
                float p3 = expf(acc[ms][ns][3] * 0.125f - m1) * s1;
                Ps[row0 * 132 + col]     = f2tf32f(p0);
                Ps[row0 * 132 + col + 1] = f2tf32f(p1);
                Ps[row1 * 132 + col]     = f2tf32f(p2);
                Ps[row1 * 132 + col + 1] = f2tf32f(p3);
                *(float2*)&awb[(size_t)row0 * SEQ + kt * 128 + col] = make_float2(p0, p1);
                *(float2*)&awb[(size_t)row1 * SEQ + kt * 128 + col] = make_float2(p2, p3);
            }
        }
        __syncthreads();

        // ctx += P @ V   (A = Ps [128 q x 128 tok], B = Vs [tok][dim])
        #pragma unroll
        for (int ks = 0; ks < 16; ks++) {
            float af[2][4], bf[4][2];
            #pragma unroll
            for (int ms = 0; ms < 2; ms++) {
                int row = wm2 + ms * 16 + g, col = ks * 8 + tg;
                af[ms][0] = Ps[row * 132 + col];
                af[ms][1] = Ps[(row + 8) * 132 + col];
                af[ms][2] = Ps[row * 132 + col + 4];
                af[ms][3] = Ps[(row + 8) * 132 + col + 4];
            }
            #pragma unroll
            for (int ns = 0; ns < 4; ns++) {
                int bc = wn2 + ns * 8 + g;
                bf[ns][0] = Vs[(ks * 8 + tg) * 72 + bc];
                bf[ns][1] = Vs[(ks * 8 + tg + 4) * 72 + bc];
            }
            #pragma unroll
            for (int ms = 0; ms < 2; ms++)
                #pragma unroll
                for (int ns = 0; ns < 4; ns++)
                    mma1688(acc2[ms][ns], af[ms], bf[ns]);
        }
        __syncthreads();
    }

    // ---- write ctx tile ----
    float* cb = ctx + (size_t)(b * SEQ + mt * 128) * DMODEL + hh * DK;
    #pragma unroll
    for (int ms = 0; ms < 2; ms++) {
        #pragma unroll
        for (int ns = 0; ns < 4; ns++) {
            int row = wm2 + ms * 16 + g;
            int col = wn2 + ns * 8 + tg * 2;
            *(float2*)&cb[(size_t)row * DMODEL + col] =
                make_float2(acc2[ms][ns][0], acc2[ms][ns][1]);
            *(float2*)&cb[(size_t)(row + 8) * DMODEL + col] =
                make_float2(acc2[ms][ns][2], acc2[ms][ns][3]);
        }
    }
}

// ------------------------- embedding + positional encoding -------------------------
__global__ void embed_kernel(const int* __restrict__ ids, const float* __restrict__ emb,
                             float* __restrict__ h) {
    int token = blockIdx.x;
    int d = blockIdx.y * 256 + threadIdx.x;
    int s = token & (SEQ - 1);
    int id = ids[token];
    float c_even = (float)((d >> 1) << 1);
    float div = __expf(c_even * (-logf(10000.0f) / (float)DMODEL));
    float ang = (float)s * div;
    float pe = (d & 1) ? cosf(ang) : sinf(ang);
    h[(size_t)token * DMODEL + d] = emb[(size_t)id * DMODEL + d] * 32.0f + pe;
}

// ------------------------- fused residual-add + LayerNorm ---------------------------
__global__ void add_ln_kernel(const float* __restrict__ x, const float* __restrict__ r,
                              const float* __restrict__ g, const float* __restrict__ b,
                              float* __restrict__ out) {
    const size_t row = blockIdx.x;
    const int tid = threadIdx.x;
    __shared__ float red[256];
    __shared__ float s_mu, s_rinv;
    float v[4];
    float s = 0.0f;
    #pragma unroll
    for (int i = 0; i < 4; i++) {
        int c = tid + i * 256;
        v[i] = x[row * DMODEL + c] + r[row * DMODEL + c];
        s += v[i];
    }
    red[tid] = s; __syncthreads();
    for (int t = 128; t > 0; t >>= 1) { if (tid < t) red[tid] += red[tid + t]; __syncthreads(); }
    if (tid == 0) s_mu = red[0] * (1.0f / DMODEL);
    __syncthreads();
    float mu = s_mu;
    float sq = 0.0f;
    #pragma unroll
    for (int i = 0; i < 4; i++) { float d = v[i] - mu; sq += d * d; }
    red[tid] = sq; __syncthreads();
    for (int t = 128; t > 0; t >>= 1) { if (tid < t) red[tid] += red[tid + t]; __syncthreads(); }
    if (tid == 0) s_rinv = rsqrtf(red[0] * (1.0f / DMODEL) + LNEPS);
    __syncthreads();
    float rinv = s_rinv;
    #pragma unroll
    for (int i = 0; i < 4; i++) {
        int c = tid + i * 256;
        out[row * DMODEL + c] = (v[i] - mu) * rinv * g[c] + b[c];
    }
}

// ====================================================================================
extern "C" void kernel_launch(void* const* d_in, const int* in_sizes, int n_in,
                              void* d_out, int out_size) {
    const int*   ids  = (const int*)  d_in[0];
    const float* emb  = (const float*)d_in[1];
    const float* Wq   = (const float*)d_in[2];
    const float* bq   = (const float*)d_in[3];
    const float* Wk   = (const float*)d_in[4];
    const float* bk   = (const float*)d_in[5];
    const float* Wv   = (const float*)d_in[6];
    const float* bv   = (const float*)d_in[7];
    const float* Wo   = (const float*)d_in[8];
    const float* bo   = (const float*)d_in[9];
    const float* W1   = (const float*)d_in[10];
    const float* b1   = (const float*)d_in[11];
    const float* W2   = (const float*)d_in[12];
    const float* b2   = (const float*)d_in[13];
    const float* ln1g = (const float*)d_in[14];
    const float* ln1b = (const float*)d_in[15];
    const float* ln2g = (const float*)d_in[16];
    const float* ln2b = (const float*)d_in[17];

    float* out = (float*)d_out;

    float *h, *q, *k, *v, *ctx, *res, *ff;
    cudaGetSymbolAddress((void**)&h,   g_h);
    cudaGetSymbolAddress((void**)&q,   g_q);
    cudaGetSymbolAddress((void**)&k,   g_k);
    cudaGetSymbolAddress((void**)&v,   g_v);
    cudaGetSymbolAddress((void**)&ctx, g_ctx);
    cudaGetSymbolAddress((void**)&res, g_res);
    cudaGetSymbolAddress((void**)&ff,  g_ff);

    cudaFuncSetAttribute(attn_fused, cudaFuncAttributeMaxDynamicSharedMemorySize,
                         FA_SMEM_BYTES);

    embed_kernel<<<dim3(TOK, DMODEL / 256), 256>>>(ids, emb, h);

    dim3 gDD(DMODEL / 128, TOK / 128);       // (8, 16)
    dim3 gDF(FF / 128, TOK / 128);           // (32, 16)
    dim3 gQKV(DMODEL / 128, TOK / 128, 3);   // (8, 16, 3)
    dim3 gFA(SEQ / 128, BATCH * NHEAD);      // (8, 32)

    for (int l = 0; l < NLAYER; l++) {
        const float* Wo_l = Wo + (size_t)l * DMODEL * DMODEL;
        const float* W1_l = W1 + (size_t)l * DMODEL * FF;
        const float* W2_l = W2 + (size_t)l * FF * DMODEL;

        float* aw = out + H_ELEMS + (size_t)l * AW_PER_LAYER;

        QKV3 p;
        p.W[0] = Wq + (size_t)l * DMODEL * DMODEL;
        p.W[1] = Wk + (size_t)l * DMODEL * DMODEL;
        p.W[2] = Wv + (size_t)l * DMODEL * DMODEL;
        p.b[0] = bq + (size_t)l * DMODEL;
        p.b[1] = bk + (size_t)l * DMODEL;
        p.b[2] = bv + (size_t)l * DMODEL;
        p.o[0] = q; p.o[1] = k; p.o[2] = v;

        gemm_qkv<<<gQKV, 256>>>(h, p);

        attn_fused<<<gFA, 256, FA_SMEM_BYTES>>>(q, k, v, aw, ctx);

        gemm_plain<0><<<gDD, 256>>>(ctx, Wo_l, bo + (size_t)l * DMODEL, res, DMODEL, DMODEL);
        add_ln_kernel<<<TOK, 256>>>(h, res, ln1g + (size_t)l * DMODEL, ln1b + (size_t)l * DMODEL, h);

        gemm_plain<1><<<gDF, 256>>>(h, W1_l, b1 + (size_t)l * FF, ff, FF, DMODEL);
        gemm_plain<0><<<gDD, 256>>>(ff, W2_l, b2 + (size_t)l * DMODEL, res, DMODEL, FF);

        float* dst = (l == NLAYER - 1) ? out : h;
        add_ln_kernel<<<TOK, 256>>>(h, res, ln2g + (size_t)l * DMODEL, ln2b + (size_t)l * DMODEL, dst);
    }
}